// round 1
// baseline (speedup 1.0000x reference)
#include <cuda_runtime.h>
#include <math.h>

// ---------------------------------------------------------------------------
// SwinV2 block: B=32, H=W=56, C=384, HEADS=12, WIN=7, SHIFT=3
// ---------------------------------------------------------------------------
#define Bb      32
#define Hh      56
#define Wwid    56
#define Cc      384
#define HEADS   12
#define HD      32
#define WIN     7
#define SHIFT   3
#define Nn49    49
#define NWY     8
#define NWX     8
#define NW      64            // windows per image
#define NWIN    (Bb*NW)       // 2048
#define TOK     (NWIN*Nn49)   // 100352  (== B*H*W)
#define HIDDEN  768

// scratch (static device globals: no allocations allowed)
__device__ float g_wnd   [(size_t)TOK * Cc];        // LN1+shift+window tokens; reused for proj out
__device__ float g_qkv   [(size_t)TOK * 3 * Cc];
__device__ float g_o     [(size_t)TOK * Cc];
__device__ float g_x2    [(size_t)TOK * Cc];        // x + attn residual (spatial layout)
__device__ float g_xm    [(size_t)TOK * Cc];        // LN2 output (spatial layout)
__device__ float g_hidden[(size_t)TOK * HIDDEN];
__device__ float g_tab   [169 * HEADS];

// ---------------------------------------------------------------------------
// CPB table:  tab[p][head],  p in [0,169) = (dh+6)*13 + (dw+6)
// ---------------------------------------------------------------------------
__device__ __forceinline__ float relcoord(int d) {
    float v = 8.0f * (float)d / 6.0f;
    return copysignf(log2f(fabsf(v) + 1.0f) * (1.0f / 3.0f), v);
}

__global__ void __launch_bounds__(256) cpb_kernel(
    const float* __restrict__ w1, const float* __restrict__ b1,
    const float* __restrict__ w2)
{
    int p  = blockIdx.x;
    float r0 = relcoord(p / 13 - 6);
    float r1 = relcoord(p % 13 - 6);
    float acc[HEADS];
#pragma unroll
    for (int h = 0; h < HEADS; h++) acc[h] = 0.f;
    for (int j = threadIdx.x; j < 512; j += 256) {
        float hv = fmaxf(r0 * w1[j*2] + r1 * w1[j*2+1] + b1[j], 0.f);
#pragma unroll
        for (int h = 0; h < HEADS; h++) acc[h] += hv * w2[h*512 + j];
    }
    __shared__ float red[256];
    for (int h = 0; h < HEADS; h++) {
        red[threadIdx.x] = acc[h];
        __syncthreads();
        for (int s = 128; s > 0; s >>= 1) {
            if (threadIdx.x < s) red[threadIdx.x] += red[threadIdx.x + s];
            __syncthreads();
        }
        if (threadIdx.x == 0) g_tab[p*HEADS + h] = red[0];
        __syncthreads();
    }
}

// ---------------------------------------------------------------------------
// LN1 + cyclic shift + window partition:  g_wnd[win*49+n][c]
// ---------------------------------------------------------------------------
__global__ void __launch_bounds__(128) ln1_kernel(
    const float* __restrict__ x, const float* __restrict__ g,
    const float* __restrict__ bb)
{
    int t   = blockIdx.x;
    int win = t / Nn49, n = t % Nn49;
    int b   = win >> 6, wi = win & 63;
    int wy  = wi >> 3,  wx = wi & 7;
    int py  = n / WIN,  px = n % WIN;
    int hh  = (wy*WIN + py + SHIFT) % Hh;
    int ww  = (wx*WIN + px + SHIFT) % Wwid;
    const float* row = x + (((size_t)b*Hh + hh)*Wwid + ww) * Cc;

    int tid = threadIdx.x;
    float4 v = make_float4(0.f, 0.f, 0.f, 0.f);
    if (tid < 96) v = ((const float4*)row)[tid];
    float s  = v.x + v.y + v.z + v.w;
    float s2 = v.x*v.x + v.y*v.y + v.z*v.z + v.w*v.w;
#pragma unroll
    for (int off = 16; off; off >>= 1) {
        s  += __shfl_xor_sync(0xffffffffu, s,  off);
        s2 += __shfl_xor_sync(0xffffffffu, s2, off);
    }
    __shared__ float rs[4], rs2[4];
    if ((tid & 31) == 0) { rs[tid>>5] = s; rs2[tid>>5] = s2; }
    __syncthreads();
    s  = rs[0]  + rs[1]  + rs[2]  + rs[3];
    s2 = rs2[0] + rs2[1] + rs2[2] + rs2[3];
    float mu  = s * (1.f/384.f);
    float var = s2 * (1.f/384.f) - mu*mu;
    float inv = rsqrtf(var + 1e-5f);
    if (tid < 96) {
        float4 gv = ((const float4*)g)[tid];
        float4 bv = ((const float4*)bb)[tid];
        float4 o;
        o.x = (v.x - mu) * inv * gv.x + bv.x;
        o.y = (v.y - mu) * inv * gv.y + bv.y;
        o.z = (v.z - mu) * inv * gv.z + bv.z;
        o.w = (v.w - mu) * inv * gv.w + bv.w;
        ((float4*)(g_wnd + (size_t)t * Cc))[tid] = o;
    }
}

// ---------------------------------------------------------------------------
// Tiled fp32 SGEMM:  C[m][n] = sum_k A[m][k]*W[n][k] + bias[n]  (+ epilogue)
// A: MxK row-major, W: NxK row-major. BM=BN=128, BK=16, 256 thr, 8x8/thread.
// All shapes used are exact multiples -> no bounds checks.
// EPI: 0 = bias, 1 = bias+exact GELU, 2 = bias + resid (final output)
// ---------------------------------------------------------------------------
template<int EPI>
__global__ void __launch_bounds__(256) sgemm_nt(
    const float* __restrict__ A, const float* __restrict__ W,
    const float* __restrict__ bias, const float* __restrict__ resid,
    float* __restrict__ Cout, int M, int Nd, int K)
{
    __shared__ float As[16][128];
    __shared__ float Bs[16][128];

    const int tid  = threadIdx.x;
    const int bm   = blockIdx.y * 128;
    const int bn   = blockIdx.x * 128;
    const int lrow = tid >> 2;          // 0..63
    const int lcol = (tid & 3) << 2;    // 0,4,8,12
    const int tx   = tid & 15;          // col group
    const int ty   = tid >> 4;          // row group

    float acc[8][8];
#pragma unroll
    for (int i = 0; i < 8; i++)
#pragma unroll
        for (int j = 0; j < 8; j++) acc[i][j] = 0.f;

    for (int k0 = 0; k0 < K; k0 += 16) {
#pragma unroll
        for (int r = 0; r < 2; r++) {
            float4 a4 = *(const float4*)&A[(size_t)(bm + lrow + 64*r) * K + k0 + lcol];
            As[lcol+0][lrow + 64*r] = a4.x;
            As[lcol+1][lrow + 64*r] = a4.y;
            As[lcol+2][lrow + 64*r] = a4.z;
            As[lcol+3][lrow + 64*r] = a4.w;
            float4 b4 = *(const float4*)&W[(size_t)(bn + lrow + 64*r) * K + k0 + lcol];
            Bs[lcol+0][lrow + 64*r] = b4.x;
            Bs[lcol+1][lrow + 64*r] = b4.y;
            Bs[lcol+2][lrow + 64*r] = b4.z;
            Bs[lcol+3][lrow + 64*r] = b4.w;
        }
        __syncthreads();
#pragma unroll
        for (int kk = 0; kk < 16; kk++) {
            float ar[8], br[8];
#pragma unroll
            for (int i = 0; i < 8; i++) ar[i] = As[kk][ty*8 + i];
#pragma unroll
            for (int j = 0; j < 8; j++) br[j] = Bs[kk][tx*8 + j];
#pragma unroll
            for (int i = 0; i < 8; i++)
#pragma unroll
                for (int j = 0; j < 8; j++) acc[i][j] += ar[i] * br[j];
        }
        __syncthreads();
    }

#pragma unroll
    for (int i = 0; i < 8; i++) {
        size_t row = (size_t)(bm + ty*8 + i);
        float* crow = Cout + row * Nd + bn + tx*8;
        const float* rrow = (EPI == 2) ? (resid + row * Nd + bn + tx*8) : nullptr;
#pragma unroll
        for (int j = 0; j < 8; j++) {
            float v = acc[i][j] + bias[bn + tx*8 + j];
            if (EPI == 1) v = 0.5f * v * (1.0f + erff(v * 0.70710678118654752f));
            if (EPI == 2) v += rrow[j];
            crow[j] = v;
        }
    }
}

// ---------------------------------------------------------------------------
// Fused window attention: one block per (window, head). 256 threads.
// ---------------------------------------------------------------------------
__global__ void __launch_bounds__(256) attn_kernel(
    const float* __restrict__ mask, const float* __restrict__ logit_scale)
{
    const int win = blockIdx.x;
    const int h   = blockIdx.y;
    const int wm  = win & 63;
    const int tid = threadIdx.x;

    __shared__ float qs[Nn49 * 33];
    __shared__ float ks[Nn49 * 33];
    __shared__ float vs[Nn49 * 33];
    __shared__ float pr[8][64];
    __shared__ float tabh[169];

    // load q,k,v (49 x 32 each), vectorized
    for (int idx = tid; idx < Nn49 * 8; idx += 256) {
        int n  = idx >> 3;
        int d4 = (idx & 7) << 2;
        const float* base = g_qkv + (size_t)(win*Nn49 + n) * (3*Cc) + h*HD + d4;
        float4 q4 = *(const float4*)(base);
        float4 k4 = *(const float4*)(base + Cc);
        float4 v4 = *(const float4*)(base + 2*Cc);
        float* qd = qs + n*33 + d4;  qd[0]=q4.x; qd[1]=q4.y; qd[2]=q4.z; qd[3]=q4.w;
        float* kd = ks + n*33 + d4;  kd[0]=k4.x; kd[1]=k4.y; kd[2]=k4.z; kd[3]=k4.w;
        float* vd = vs + n*33 + d4;  vd[0]=v4.x; vd[1]=v4.y; vd[2]=v4.z; vd[3]=v4.w;
    }
    if (tid < 169) tabh[tid] = g_tab[tid*HEADS + h];
    __syncthreads();

    const float scale_h = expf(fminf(logit_scale[h], 4.6051701859880914f));

    // L2-normalize q,k rows; fold logit scale into q
    if (tid < 98) {
        int isQ = (tid < Nn49);
        float* row = isQ ? (qs + tid*33) : (ks + (tid - Nn49)*33);
        float ss = 0.f;
#pragma unroll
        for (int d = 0; d < HD; d++) ss += row[d]*row[d];
        float inv = 1.0f / fmaxf(sqrtf(ss), 1e-12f);
        if (isQ) inv *= scale_h;
#pragma unroll
        for (int d = 0; d < HD; d++) row[d] *= inv;
    }
    __syncthreads();

    const int warp = tid >> 5, lane = tid & 31;
    for (int i = warp; i < Nn49; i += 8) {
        int ri = i / WIN, ci = i % WIN;
        float l0, l1 = -1e30f;
        {
            int j = lane;
            float acc = 0.f;
#pragma unroll
            for (int d = 0; d < HD; d++) acc += qs[i*33 + d] * ks[j*33 + d];
            int di = (ri - j/WIN + 6)*13 + (ci - j%WIN + 6);
            float rpb = 16.f / (1.f + expf(-tabh[di]));
            l0 = acc + rpb + mask[(size_t)wm*2401 + i*Nn49 + j];
        }
        if (lane < 17) {
            int j = lane + 32;
            float acc = 0.f;
#pragma unroll
            for (int d = 0; d < HD; d++) acc += qs[i*33 + d] * ks[j*33 + d];
            int di = (ri - j/WIN + 6)*13 + (ci - j%WIN + 6);
            float rpb = 16.f / (1.f + expf(-tabh[di]));
            l1 = acc + rpb + mask[(size_t)wm*2401 + i*Nn49 + j];
        }
        float m = fmaxf(l0, l1);
#pragma unroll
        for (int off = 16; off; off >>= 1)
            m = fmaxf(m, __shfl_xor_sync(0xffffffffu, m, off));
        float e0 = expf(l0 - m);
        float e1 = (lane < 17) ? expf(l1 - m) : 0.f;
        float s = e0 + e1;
#pragma unroll
        for (int off = 16; off; off >>= 1)
            s += __shfl_xor_sync(0xffffffffu, s, off);
        float invs = 1.0f / s;
        pr[warp][lane]      = e0 * invs;
        pr[warp][lane + 32] = e1 * invs;
        __syncwarp();

        float acc = 0.f;
        int d = lane;
#pragma unroll
        for (int j = 0; j < Nn49; j++) acc += pr[warp][j] * vs[j*33 + d];
        g_o[(size_t)(win*Nn49 + i) * Cc + h*HD + d] = acc;
    }
}

// ---------------------------------------------------------------------------
// window-reverse + un-shift + residual + LN2: g_x2 and g_xm (spatial layout)
// ---------------------------------------------------------------------------
__global__ void __launch_bounds__(128) ln2_kernel(
    const float* __restrict__ x, const float* __restrict__ g,
    const float* __restrict__ bb)
{
    int s_tok = blockIdx.x;                        // spatial token: b*3136 + hh*56 + ww
    int b   = s_tok / (Hh*Wwid);
    int rem = s_tok % (Hh*Wwid);
    int hh  = rem / Wwid, ww = rem % Wwid;
    int sh  = (hh + Hh - SHIFT) % Hh;
    int sw  = (ww + Wwid - SHIFT) % Wwid;
    int wy  = sh / WIN, py = sh % WIN;
    int wx  = sw / WIN, px = sw % WIN;
    size_t ptok = ((size_t)(b*NW + wy*NWX + wx) * Nn49 + py*WIN + px);

    const float* xrow = x     + (size_t)s_tok * Cc;
    const float* prow = g_wnd + ptok * Cc;         // proj output lives in g_wnd

    int tid = threadIdx.x;
    float4 v = make_float4(0.f, 0.f, 0.f, 0.f);
    if (tid < 96) {
        float4 xv = ((const float4*)xrow)[tid];
        float4 pv = ((const float4*)prow)[tid];
        v = make_float4(xv.x + pv.x, xv.y + pv.y, xv.z + pv.z, xv.w + pv.w);
    }
    float s  = v.x + v.y + v.z + v.w;
    float s2 = v.x*v.x + v.y*v.y + v.z*v.z + v.w*v.w;
#pragma unroll
    for (int off = 16; off; off >>= 1) {
        s  += __shfl_xor_sync(0xffffffffu, s,  off);
        s2 += __shfl_xor_sync(0xffffffffu, s2, off);
    }
    __shared__ float rs[4], rs2[4];
    if ((tid & 31) == 0) { rs[tid>>5] = s; rs2[tid>>5] = s2; }
    __syncthreads();
    s  = rs[0]  + rs[1]  + rs[2]  + rs[3];
    s2 = rs2[0] + rs2[1] + rs2[2] + rs2[3];
    float mu  = s * (1.f/384.f);
    float var = s2 * (1.f/384.f) - mu*mu;
    float inv = rsqrtf(var + 1e-5f);
    if (tid < 96) {
        ((float4*)(g_x2 + (size_t)s_tok * Cc))[tid] = v;
        float4 gv = ((const float4*)g)[tid];
        float4 bv = ((const float4*)bb)[tid];
        float4 o;
        o.x = (v.x - mu) * inv * gv.x + bv.x;
        o.y = (v.y - mu) * inv * gv.y + bv.y;
        o.z = (v.z - mu) * inv * gv.z + bv.z;
        o.w = (v.w - mu) * inv * gv.w + bv.w;
        ((float4*)(g_xm + (size_t)s_tok * Cc))[tid] = o;
    }
}

// ---------------------------------------------------------------------------
extern "C" void kernel_launch(void* const* d_in, const int* in_sizes, int n_in,
                              void* d_out, int out_size)
{
    const float* x       = (const float*)d_in[0];
    const float* mask    = (const float*)d_in[1];
    const float* n1g     = (const float*)d_in[2];
    const float* n1b     = (const float*)d_in[3];
    const float* qkv_w   = (const float*)d_in[4];
    const float* qkv_b   = (const float*)d_in[5];
    const float* proj_w  = (const float*)d_in[6];
    const float* proj_b  = (const float*)d_in[7];
    const float* cpb_w1  = (const float*)d_in[8];
    const float* cpb_b1  = (const float*)d_in[9];
    const float* cpb_w2  = (const float*)d_in[10];
    const float* lscale  = (const float*)d_in[11];
    const float* n2g     = (const float*)d_in[12];
    const float* n2b     = (const float*)d_in[13];
    const float* mlp_w1  = (const float*)d_in[14];
    const float* mlp_b1  = (const float*)d_in[15];
    const float* mlp_w2  = (const float*)d_in[16];
    const float* mlp_b2  = (const float*)d_in[17];
    float* out = (float*)d_out;

    float* wnd    = nullptr; cudaGetSymbolAddress((void**)&wnd,    g_wnd);
    float* qkv    = nullptr; cudaGetSymbolAddress((void**)&qkv,    g_qkv);
    float* obuf   = nullptr; cudaGetSymbolAddress((void**)&obuf,   g_o);
    float* x2     = nullptr; cudaGetSymbolAddress((void**)&x2,     g_x2);
    float* xm     = nullptr; cudaGetSymbolAddress((void**)&xm,     g_xm);
    float* hidden = nullptr; cudaGetSymbolAddress((void**)&hidden, g_hidden);

    // 1. CPB table
    cpb_kernel<<<169, 256>>>(cpb_w1, cpb_b1, cpb_w2);
    // 2. LN1 + shift + window partition
    ln1_kernel<<<TOK, 128>>>(x, n1g, n1b);
    // 3. QKV GEMM: (100352 x 384) @ (1152 x 384)^T
    sgemm_nt<0><<<dim3(1152/128, TOK/128), 256>>>(wnd, qkv_w, qkv_b, nullptr, qkv, TOK, 3*Cc, Cc);
    // 4. fused window attention
    attn_kernel<<<dim3(NWIN, HEADS), 256>>>(mask, lscale);
    // 5. proj GEMM (output reuses g_wnd)
    sgemm_nt<0><<<dim3(Cc/128, TOK/128), 256>>>(obuf, proj_w, proj_b, nullptr, wnd, TOK, Cc, Cc);
    // 6. window-reverse + residual + LN2
    ln2_kernel<<<TOK, 128>>>(x, n2g, n2b);
    // 7. MLP1 + GELU
    sgemm_nt<1><<<dim3(HIDDEN/128, TOK/128), 256>>>(xm, mlp_w1, mlp_b1, nullptr, hidden, TOK, HIDDEN, Cc);
    // 8. MLP2 + residual -> d_out
    sgemm_nt<2><<<dim3(Cc/128, TOK/128), 256>>>(hidden, mlp_w2, mlp_b2, x2, out, TOK, Cc, HIDDEN);
}

// round 3
// speedup vs baseline: 3.2999x; 3.2999x over previous
#include <cuda_runtime.h>
#include <cuda_fp16.h>
#include <cstdint>
#include <math.h>

// ---------------------------------------------------------------------------
// SwinV2 block: B=32, H=W=56, C=384, HEADS=12, WIN=7, SHIFT=3
// ---------------------------------------------------------------------------
#define Bb      32
#define Hh      56
#define Wwid    56
#define Cc      384
#define HEADS   12
#define HD      32
#define WIN     7
#define SHIFT   3
#define Nn49    49
#define NW      64
#define NWIN    (Bb*NW)       // 2048
#define TOK     (NWIN*Nn49)   // 100352
#define HIDDEN  768

// scratch (static device globals)
__device__ __half g_a      [(size_t)TOK * Cc];      // LN1 output (fp16)
__device__ __half g_qkv    [(size_t)TOK * 3 * Cc];
__device__ __half g_o      [(size_t)TOK * Cc];      // attention output (fp16)
__device__ float  g_projout[(size_t)TOK * Cc];      // proj output (fp32)
__device__ float  g_x2     [(size_t)TOK * Cc];      // x + attn residual
__device__ __half g_xm     [(size_t)TOK * Cc];      // LN2 output (fp16)
__device__ __half g_hidden [(size_t)TOK * HIDDEN];  // GELU output (fp16)
__device__ float  g_tab    [169 * HEADS];
// fp16 weights
__device__ __half g_wqkv [3*Cc*Cc];
__device__ __half g_wproj[Cc*Cc];
__device__ __half g_wm1  [HIDDEN*Cc];
__device__ __half g_wm2  [Cc*HIDDEN];

// ---------------------------------------------------------------------------
__global__ void __launch_bounds__(256) f2h_kernel(const float* __restrict__ s,
                                                  __half* __restrict__ d, int n)
{
    int i = blockIdx.x * 256 + threadIdx.x;
    if (i < n) d[i] = __float2half(s[i]);
}

// ---------------------------------------------------------------------------
// CPB table: tab[p][head], p = (dh+6)*13 + (dw+6)
// ---------------------------------------------------------------------------
__device__ __forceinline__ float relcoord(int d) {
    float v = 8.0f * (float)d / 6.0f;
    return copysignf(log2f(fabsf(v) + 1.0f) * (1.0f / 3.0f), v);
}

__global__ void __launch_bounds__(256) cpb_kernel(
    const float* __restrict__ w1, const float* __restrict__ b1,
    const float* __restrict__ w2)
{
    int p  = blockIdx.x;
    float r0 = relcoord(p / 13 - 6);
    float r1 = relcoord(p % 13 - 6);
    float acc[HEADS];
#pragma unroll
    for (int h = 0; h < HEADS; h++) acc[h] = 0.f;
    for (int j = threadIdx.x; j < 512; j += 256) {
        float hv = fmaxf(r0 * w1[j*2] + r1 * w1[j*2+1] + b1[j], 0.f);
#pragma unroll
        for (int h = 0; h < HEADS; h++) acc[h] += hv * w2[h*512 + j];
    }
    __shared__ float red[256];
    for (int h = 0; h < HEADS; h++) {
        red[threadIdx.x] = acc[h];
        __syncthreads();
        for (int s = 128; s > 0; s >>= 1) {
            if (threadIdx.x < s) red[threadIdx.x] += red[threadIdx.x + s];
            __syncthreads();
        }
        if (threadIdx.x == 0) g_tab[p*HEADS + h] = red[0];
        __syncthreads();
    }
}

// ---------------------------------------------------------------------------
// LN1 + cyclic shift + window partition -> g_a (fp16)
// ---------------------------------------------------------------------------
__global__ void __launch_bounds__(128) ln1_kernel(
    const float* __restrict__ x, const float* __restrict__ g,
    const float* __restrict__ bb)
{
    int t   = blockIdx.x;
    int win = t / Nn49, n = t % Nn49;
    int b   = win >> 6, wi = win & 63;
    int wy  = wi >> 3,  wx = wi & 7;
    int py  = n / WIN,  px = n % WIN;
    int hh  = (wy*WIN + py + SHIFT) % Hh;
    int ww  = (wx*WIN + px + SHIFT) % Wwid;
    const float* row = x + (((size_t)b*Hh + hh)*Wwid + ww) * Cc;

    int tid = threadIdx.x;
    float4 v = make_float4(0.f, 0.f, 0.f, 0.f);
    if (tid < 96) v = ((const float4*)row)[tid];
    float s  = v.x + v.y + v.z + v.w;
    float s2 = v.x*v.x + v.y*v.y + v.z*v.z + v.w*v.w;
#pragma unroll
    for (int off = 16; off; off >>= 1) {
        s  += __shfl_xor_sync(0xffffffffu, s,  off);
        s2 += __shfl_xor_sync(0xffffffffu, s2, off);
    }
    __shared__ float rs[4], rs2[4];
    if ((tid & 31) == 0) { rs[tid>>5] = s; rs2[tid>>5] = s2; }
    __syncthreads();
    s  = rs[0]  + rs[1]  + rs[2]  + rs[3];
    s2 = rs2[0] + rs2[1] + rs2[2] + rs2[3];
    float mu  = s * (1.f/384.f);
    float var = s2 * (1.f/384.f) - mu*mu;
    float inv = rsqrtf(var + 1e-5f);
    if (tid < 96) {
        float4 gv = ((const float4*)g)[tid];
        float4 bv = ((const float4*)bb)[tid];
        __half2 h0 = __floats2half2_rn((v.x - mu)*inv*gv.x + bv.x,
                                       (v.y - mu)*inv*gv.y + bv.y);
        __half2 h1 = __floats2half2_rn((v.z - mu)*inv*gv.z + bv.z,
                                       (v.w - mu)*inv*gv.w + bv.w);
        __half2* dst = (__half2*)(g_a + (size_t)t * Cc + tid*4);
        dst[0] = h0; dst[1] = h1;
    }
}

// ---------------------------------------------------------------------------
// fp16 tensor-core GEMM: C[m][n] = sum_k A[m][k] * W[n][k] + bias[n] (+epi)
// BM=BN=128, BK=32, 256 threads (8 warps, 2x4), warp tile 64x32.
// EPI: 0 = fp16 out, bias;  1 = fp16 out, bias+GELU;
//      2 = fp32 out, bias;  3 = fp32 out, bias+resid
// ---------------------------------------------------------------------------
#define LDSM4(r0,r1,r2,r3,addr) \
    asm volatile("ldmatrix.sync.aligned.m8n8.x4.shared.b16 {%0,%1,%2,%3}, [%4];" \
        : "=r"(r0),"=r"(r1),"=r"(r2),"=r"(r3) : "r"(addr))

#define MMA16816(c, a, b) \
    asm volatile("mma.sync.aligned.m16n8k16.row.col.f32.f16.f16.f32 " \
        "{%0,%1,%2,%3},{%4,%5,%6,%7},{%8,%9},{%0,%1,%2,%3};" \
        : "+f"(c[0]),"+f"(c[1]),"+f"(c[2]),"+f"(c[3]) \
        : "r"(a[0]),"r"(a[1]),"r"(a[2]),"r"(a[3]),"r"(b[0]),"r"(b[1]))

__device__ __forceinline__ uint32_t smem_u32(const void* p) {
    return (uint32_t)__cvta_generic_to_shared(p);
}
__device__ __forceinline__ void cp_async16(uint32_t dst, const void* src) {
    asm volatile("cp.async.cg.shared.global [%0], [%1], 16;" :: "r"(dst), "l"(src));
}

template<int EPI>
__global__ void __launch_bounds__(256) hgemm(
    const __half* __restrict__ A, const __half* __restrict__ Wt,
    const float* __restrict__ bias, const float* __restrict__ resid,
    void* __restrict__ Cptr, int M, int Nd, int K)
{
    __shared__ __half As[2][128*40];
    __shared__ __half Bs[2][128*40];

    const int tid  = threadIdx.x;
    const int bm   = blockIdx.y * 128;
    const int bn   = blockIdx.x * 128;
    const int wid  = tid >> 5, lane = tid & 31;
    const int wm   = (wid & 1) * 64;
    const int wn   = (wid >> 1) * 32;

    float acc[4][4][4];
#pragma unroll
    for (int mi = 0; mi < 4; mi++)
#pragma unroll
        for (int ni = 0; ni < 4; ni++)
#pragma unroll
            for (int q = 0; q < 4; q++) acc[mi][ni][q] = 0.f;

    const int lr = tid >> 2;          // 0..63
    const int lc = (tid & 3) * 8;     // 0,8,16,24 (halves)

    // prologue: stage 0
    {
#pragma unroll
        for (int i = 0; i < 2; i++) {
            int row = lr + i*64;
            cp_async16(smem_u32(&As[0][row*40 + lc]), A  + (size_t)(bm+row)*K + lc);
            cp_async16(smem_u32(&Bs[0][row*40 + lc]), Wt + (size_t)(bn+row)*K + lc);
        }
        asm volatile("cp.async.commit_group;");
    }

    const int nk = K >> 5;
    for (int kt = 0; kt < nk; kt++) {
        const int s = kt & 1;
        if (kt + 1 < nk) {
            int k0 = (kt+1) << 5;
#pragma unroll
            for (int i = 0; i < 2; i++) {
                int row = lr + i*64;
                cp_async16(smem_u32(&As[s^1][row*40 + lc]), A  + (size_t)(bm+row)*K + k0 + lc);
                cp_async16(smem_u32(&Bs[s^1][row*40 + lc]), Wt + (size_t)(bn+row)*K + k0 + lc);
            }
            asm volatile("cp.async.commit_group;");
            asm volatile("cp.async.wait_group 1;");
        } else {
            asm volatile("cp.async.wait_group 0;");
        }
        __syncthreads();

#pragma unroll
        for (int kk = 0; kk < 2; kk++) {
            uint32_t a[4][4], b[4][2];
#pragma unroll
            for (int mi = 0; mi < 4; mi++) {
                int row = wm + mi*16 + (lane & 15);
                int col = kk*16 + ((lane >> 4) << 3);
                uint32_t ad = smem_u32(&As[s][row*40 + col]);
                LDSM4(a[mi][0], a[mi][1], a[mi][2], a[mi][3], ad);
            }
#pragma unroll
            for (int bi = 0; bi < 2; bi++) {
                int n   = wn + bi*16 + ((lane >> 4) << 3) + (lane & 7);
                int col = kk*16 + ((lane >> 3) & 1) * 8;
                uint32_t ad = smem_u32(&Bs[s][n*40 + col]);
                uint32_t t0, t1, t2, t3;
                LDSM4(t0, t1, t2, t3, ad);
                b[bi*2+0][0] = t0; b[bi*2+0][1] = t1;
                b[bi*2+1][0] = t2; b[bi*2+1][1] = t3;
            }
#pragma unroll
            for (int mi = 0; mi < 4; mi++)
#pragma unroll
                for (int ni = 0; ni < 4; ni++)
                    MMA16816(acc[mi][ni], a[mi], b[ni]);
        }
        __syncthreads();
    }

    // epilogue
    const int er = lane >> 2, ec = (lane & 3) * 2;
#pragma unroll
    for (int mi = 0; mi < 4; mi++) {
#pragma unroll
        for (int ni = 0; ni < 4; ni++) {
            int col = bn + wn + ni*8 + ec;
            float b0 = bias[col], b1 = bias[col+1];
#pragma unroll
            for (int hh = 0; hh < 2; hh++) {
                size_t row = (size_t)(bm + wm + mi*16 + er + hh*8);
                float v0 = acc[mi][ni][hh*2+0] + b0;
                float v1 = acc[mi][ni][hh*2+1] + b1;
                if (EPI == 1) {
                    v0 = 0.5f * v0 * (1.0f + erff(v0 * 0.70710678118654752f));
                    v1 = 0.5f * v1 * (1.0f + erff(v1 * 0.70710678118654752f));
                }
                if (EPI == 3) {
                    const float* rr = resid + row * Nd + col;
                    v0 += rr[0]; v1 += rr[1];
                }
                if (EPI == 0 || EPI == 1) {
                    *(__half2*)((__half*)Cptr + row * Nd + col) = __floats2half2_rn(v0, v1);
                } else {
                    float2 f; f.x = v0; f.y = v1;
                    *(float2*)((float*)Cptr + row * Nd + col) = f;
                }
            }
        }
    }
}

// ---------------------------------------------------------------------------
// Fused window attention: one block per (window, head). 256 threads. fp16 I/O.
// ---------------------------------------------------------------------------
__global__ void __launch_bounds__(256) attn_kernel(
    const float* __restrict__ mask, const float* __restrict__ logit_scale)
{
    const int win = blockIdx.x;
    const int h   = blockIdx.y;
    const int wm  = win & 63;
    const int tid = threadIdx.x;

    __shared__ float qs[Nn49 * 33];
    __shared__ float ks[Nn49 * 33];
    __shared__ float vs[Nn49 * 33];
    __shared__ float pr[8][64];
    __shared__ float tabh[169];

    // load q,k,v (49 x 32 halves each)
    for (int idx = tid; idx < Nn49 * 4; idx += 256) {
        int n  = idx >> 2;
        int d8 = (idx & 3) << 3;
        const __half* base = g_qkv + (size_t)(win*Nn49 + n) * (3*Cc) + h*HD + d8;
        uint4 qv = *(const uint4*)(base);
        uint4 kv = *(const uint4*)(base + Cc);
        uint4 vv = *(const uint4*)(base + 2*Cc);
        const __half2* q2 = (const __half2*)&qv;
        const __half2* k2 = (const __half2*)&kv;
        const __half2* v2 = (const __half2*)&vv;
#pragma unroll
        for (int j = 0; j < 4; j++) {
            float2 f;
            f = __half22float2(q2[j]); qs[n*33 + d8 + 2*j] = f.x; qs[n*33 + d8 + 2*j + 1] = f.y;
            f = __half22float2(k2[j]); ks[n*33 + d8 + 2*j] = f.x; ks[n*33 + d8 + 2*j + 1] = f.y;
            f = __half22float2(v2[j]); vs[n*33 + d8 + 2*j] = f.x; vs[n*33 + d8 + 2*j + 1] = f.y;
        }
    }
    if (tid < 169) tabh[tid] = g_tab[tid*HEADS + h];
    __syncthreads();

    const float scale_h = expf(fminf(logit_scale[h], 4.6051701859880914f));

    if (tid < 98) {
        int isQ = (tid < Nn49);
        float* row = isQ ? (qs + tid*33) : (ks + (tid - Nn49)*33);
        float ss = 0.f;
#pragma unroll
        for (int d = 0; d < HD; d++) ss += row[d]*row[d];
        float inv = 1.0f / fmaxf(sqrtf(ss), 1e-12f);
        if (isQ) inv *= scale_h;
#pragma unroll
        for (int d = 0; d < HD; d++) row[d] *= inv;
    }
    __syncthreads();

    const int warp = tid >> 5, lane = tid & 31;
    for (int i = warp; i < Nn49; i += 8) {
        int ri = i / WIN, ci = i % WIN;
        float l0, l1 = -1e30f;
        {
            int j = lane;
            float acc = 0.f;
#pragma unroll
            for (int d = 0; d < HD; d++) acc += qs[i*33 + d] * ks[j*33 + d];
            int di = (ri - j/WIN + 6)*13 + (ci - j%WIN + 6);
            float rpb = 16.f / (1.f + expf(-tabh[di]));
            l0 = acc + rpb + mask[(size_t)wm*2401 + i*Nn49 + j];
        }
        if (lane < 17) {
            int j = lane + 32;
            float acc = 0.f;
#pragma unroll
            for (int d = 0; d < HD; d++) acc += qs[i*33 + d] * ks[j*33 + d];
            int di = (ri - j/WIN + 6)*13 + (ci - j%WIN + 6);
            float rpb = 16.f / (1.f + expf(-tabh[di]));
            l1 = acc + rpb + mask[(size_t)wm*2401 + i*Nn49 + j];
        }
        float m = fmaxf(l0, l1);
#pragma unroll
        for (int off = 16; off; off >>= 1)
            m = fmaxf(m, __shfl_xor_sync(0xffffffffu, m, off));
        float e0 = expf(l0 - m);
        float e1 = (lane < 17) ? expf(l1 - m) : 0.f;
        float sje = e0 + e1;
#pragma unroll
        for (int off = 16; off; off >>= 1)
            sje += __shfl_xor_sync(0xffffffffu, sje, off);
        float invs = 1.0f / sje;
        pr[warp][lane]      = e0 * invs;
        pr[warp][lane + 32] = e1 * invs;
        __syncwarp();

        float acc = 0.f;
        int d = lane;
#pragma unroll
        for (int j = 0; j < Nn49; j++) acc += pr[warp][j] * vs[j*33 + d];
        g_o[(size_t)(win*Nn49 + i) * Cc + h*HD + d] = __float2half(acc);
    }
}

// ---------------------------------------------------------------------------
// window-reverse + un-shift + residual + LN2 -> g_x2 (fp32), g_xm (fp16)
// ---------------------------------------------------------------------------
__global__ void __launch_bounds__(128) ln2_kernel(
    const float* __restrict__ x, const float* __restrict__ g,
    const float* __restrict__ bb)
{
    int s_tok = blockIdx.x;
    int b   = s_tok / (Hh*Wwid);
    int rem = s_tok % (Hh*Wwid);
    int hh  = rem / Wwid, ww = rem % Wwid;
    int sh  = (hh + Hh - SHIFT) % Hh;
    int sw  = (ww + Wwid - SHIFT) % Wwid;
    int wy  = sh / WIN, py = sh % WIN;
    int wx  = sw / WIN, px = sw % WIN;
    size_t ptok = ((size_t)(b*NW + wy*8 + wx) * Nn49 + py*WIN + px);

    const float* xrow = x         + (size_t)s_tok * Cc;
    const float* prow = g_projout + ptok * Cc;

    int tid = threadIdx.x;
    float4 v = make_float4(0.f, 0.f, 0.f, 0.f);
    if (tid < 96) {
        float4 xv = ((const float4*)xrow)[tid];
        float4 pv = ((const float4*)prow)[tid];
        v = make_float4(xv.x + pv.x, xv.y + pv.y, xv.z + pv.z, xv.w + pv.w);
    }
    float s  = v.x + v.y + v.z + v.w;
    float s2 = v.x*v.x + v.y*v.y + v.z*v.z + v.w*v.w;
#pragma unroll
    for (int off = 16; off; off >>= 1) {
        s  += __shfl_xor_sync(0xffffffffu, s,  off);
        s2 += __shfl_xor_sync(0xffffffffu, s2, off);
    }
    __shared__ float rs[4], rs2[4];
    if ((tid & 31) == 0) { rs[tid>>5] = s; rs2[tid>>5] = s2; }
    __syncthreads();
    s  = rs[0]  + rs[1]  + rs[2]  + rs[3];
    s2 = rs2[0] + rs2[1] + rs2[2] + rs2[3];
    float mu  = s * (1.f/384.f);
    float var = s2 * (1.f/384.f) - mu*mu;
    float inv = rsqrtf(var + 1e-5f);
    if (tid < 96) {
        ((float4*)(g_x2 + (size_t)s_tok * Cc))[tid] = v;
        float4 gv = ((const float4*)g)[tid];
        float4 bv = ((const float4*)bb)[tid];
        __half2 h0 = __floats2half2_rn((v.x - mu)*inv*gv.x + bv.x,
                                       (v.y - mu)*inv*gv.y + bv.y);
        __half2 h1 = __floats2half2_rn((v.z - mu)*inv*gv.z + bv.z,
                                       (v.w - mu)*inv*gv.w + bv.w);
        __half2* dst = (__half2*)(g_xm + (size_t)s_tok * Cc + tid*4);
        dst[0] = h0; dst[1] = h1;
    }
}

// ---------------------------------------------------------------------------
extern "C" void kernel_launch(void* const* d_in, const int* in_sizes, int n_in,
                              void* d_out, int out_size)
{
    const float* x       = (const float*)d_in[0];
    const float* mask    = (const float*)d_in[1];
    const float* n1g     = (const float*)d_in[2];
    const float* n1b     = (const float*)d_in[3];
    const float* qkv_w   = (const float*)d_in[4];
    const float* qkv_b   = (const float*)d_in[5];
    const float* proj_w  = (const float*)d_in[6];
    const float* proj_b  = (const float*)d_in[7];
    const float* cpb_w1  = (const float*)d_in[8];
    const float* cpb_b1  = (const float*)d_in[9];
    const float* cpb_w2  = (const float*)d_in[10];
    const float* lscale  = (const float*)d_in[11];
    const float* n2g     = (const float*)d_in[12];
    const float* n2b     = (const float*)d_in[13];
    const float* mlp_w1  = (const float*)d_in[14];
    const float* mlp_b1  = (const float*)d_in[15];
    const float* mlp_w2  = (const float*)d_in[16];
    const float* mlp_b2  = (const float*)d_in[17];
    float* out = (float*)d_out;

    __half *a=nullptr, *qkv=nullptr, *o=nullptr, *xm=nullptr, *hidden=nullptr;
    __half *wqkv=nullptr, *wproj=nullptr, *wm1=nullptr, *wm2=nullptr;
    float *projout=nullptr, *x2=nullptr;
    cudaGetSymbolAddress((void**)&a,       g_a);
    cudaGetSymbolAddress((void**)&qkv,     g_qkv);
    cudaGetSymbolAddress((void**)&o,       g_o);
    cudaGetSymbolAddress((void**)&projout, g_projout);
    cudaGetSymbolAddress((void**)&x2,      g_x2);
    cudaGetSymbolAddress((void**)&xm,      g_xm);
    cudaGetSymbolAddress((void**)&hidden,  g_hidden);
    cudaGetSymbolAddress((void**)&wqkv,    g_wqkv);
    cudaGetSymbolAddress((void**)&wproj,   g_wproj);
    cudaGetSymbolAddress((void**)&wm1,     g_wm1);
    cudaGetSymbolAddress((void**)&wm2,     g_wm2);

    // weight conversion fp32 -> fp16
    f2h_kernel<<<(3*Cc*Cc + 255)/256, 256>>>(qkv_w,  wqkv,  3*Cc*Cc);
    f2h_kernel<<<(Cc*Cc + 255)/256,   256>>>(proj_w, wproj, Cc*Cc);
    f2h_kernel<<<(HIDDEN*Cc + 255)/256, 256>>>(mlp_w1, wm1, HIDDEN*Cc);
    f2h_kernel<<<(Cc*HIDDEN + 255)/256, 256>>>(mlp_w2, wm2, Cc*HIDDEN);

    // CPB table
    cpb_kernel<<<169, 256>>>(cpb_w1, cpb_b1, cpb_w2);
    // LN1 + shift + window partition
    ln1_kernel<<<TOK, 128>>>(x, n1g, n1b);
    // QKV GEMM: (100352 x 384) @ (1152 x 384)^T -> fp16
    hgemm<0><<<dim3(9, TOK/128), 256>>>(a, wqkv, qkv_b, nullptr, qkv, TOK, 3*Cc, Cc);
    // fused window attention
    attn_kernel<<<dim3(NWIN, HEADS), 256>>>(mask, lscale);
    // proj GEMM -> fp32
    hgemm<2><<<dim3(3, TOK/128), 256>>>(o, wproj, proj_b, nullptr, projout, TOK, Cc, Cc);
    // window-reverse + residual + LN2
    ln2_kernel<<<TOK, 128>>>(x, n2g, n2b);
    // MLP1 + GELU -> fp16
    hgemm<1><<<dim3(6, TOK/128), 256>>>(xm, wm1, mlp_b1, nullptr, hidden, TOK, HIDDEN, Cc);
    // MLP2 + residual -> d_out (fp32)
    hgemm<3><<<dim3(3, TOK/128), 256>>>(hidden, wm2, mlp_b2, x2, out, TOK, Cc, HIDDEN);
}

// round 4
// speedup vs baseline: 4.9981x; 1.5146x over previous
#include <cuda_runtime.h>
#include <cuda_fp16.h>
#include <cstdint>
#include <math.h>

// ---------------------------------------------------------------------------
// SwinV2 block: B=32, H=W=56, C=384, HEADS=12, WIN=7, SHIFT=3
// ---------------------------------------------------------------------------
#define Bb      32
#define Hh      56
#define Wwid    56
#define Cc      384
#define HEADS   12
#define HD      32
#define WIN     7
#define SHIFT   3
#define Nn49    49
#define NW      64
#define NWIN    (Bb*NW)       // 2048
#define TOK     (NWIN*Nn49)   // 100352
#define HIDDEN  768

// scratch (static device globals)
__device__ __half g_a      [(size_t)TOK * Cc];      // LN1 output (fp16)
__device__ __half g_qkv    [(size_t)TOK * 3 * Cc];
__device__ __half g_o      [(size_t)TOK * Cc];      // attention output (fp16)
__device__ float  g_projout[(size_t)TOK * Cc];      // proj output (fp32)
__device__ float  g_x2     [(size_t)TOK * Cc];      // x + attn residual
__device__ __half g_xm     [(size_t)TOK * Cc];      // LN2 output (fp16)
__device__ __half g_hidden [(size_t)TOK * HIDDEN];  // GELU output (fp16)
__device__ float  g_tab    [169 * HEADS];
__device__ float  g_bias   [(size_t)NW * HEADS * Nn49 * Nn49]; // rpb+mask table
// fp16 weights
__device__ __half g_wqkv [3*Cc*Cc];
__device__ __half g_wproj[Cc*Cc];
__device__ __half g_wm1  [HIDDEN*Cc];
__device__ __half g_wm2  [Cc*HIDDEN];

// ---------------------------------------------------------------------------
__global__ void __launch_bounds__(256) f2h_kernel(const float* __restrict__ s,
                                                  __half* __restrict__ d, int n)
{
    int i = blockIdx.x * 256 + threadIdx.x;
    if (i < n) d[i] = __float2half(s[i]);
}

// ---------------------------------------------------------------------------
// CPB table: tab[p][head], p = (dh+6)*13 + (dw+6)
// ---------------------------------------------------------------------------
__device__ __forceinline__ float relcoord(int d) {
    float v = 8.0f * (float)d / 6.0f;
    return copysignf(log2f(fabsf(v) + 1.0f) * (1.0f / 3.0f), v);
}

__global__ void __launch_bounds__(256) cpb_kernel(
    const float* __restrict__ w1, const float* __restrict__ b1,
    const float* __restrict__ w2)
{
    int p  = blockIdx.x;
    float r0 = relcoord(p / 13 - 6);
    float r1 = relcoord(p % 13 - 6);
    float acc[HEADS];
#pragma unroll
    for (int h = 0; h < HEADS; h++) acc[h] = 0.f;
    for (int j = threadIdx.x; j < 512; j += 256) {
        float hv = fmaxf(r0 * w1[j*2] + r1 * w1[j*2+1] + b1[j], 0.f);
#pragma unroll
        for (int h = 0; h < HEADS; h++) acc[h] += hv * w2[h*512 + j];
    }
    __shared__ float red[256];
    for (int h = 0; h < HEADS; h++) {
        red[threadIdx.x] = acc[h];
        __syncthreads();
        for (int s = 128; s > 0; s >>= 1) {
            if (threadIdx.x < s) red[threadIdx.x] += red[threadIdx.x + s];
            __syncthreads();
        }
        if (threadIdx.x == 0) g_tab[p*HEADS + h] = red[0];
        __syncthreads();
    }
}

// ---------------------------------------------------------------------------
// bias table: bias[wm][h][i][j] = 16*sigmoid(tab) + mask
// ---------------------------------------------------------------------------
__global__ void __launch_bounds__(256) bias_kernel(const float* __restrict__ mask)
{
    int wm = blockIdx.x, h = blockIdx.y;
    float* dst = g_bias + ((size_t)wm*HEADS + h) * (Nn49*Nn49);
    const float* msk = mask + (size_t)wm * (Nn49*Nn49);
    for (int e = threadIdx.x; e < Nn49*Nn49; e += 256) {
        int i = e / Nn49, j = e % Nn49;
        int di = (i/WIN - j/WIN + 6)*13 + (i%WIN - j%WIN + 6);
        float t = g_tab[di*HEADS + h];
        dst[e] = 16.f / (1.f + __expf(-t)) + msk[e];
    }
}

// ---------------------------------------------------------------------------
// LN1 + cyclic shift + window partition -> g_a (fp16)
// ---------------------------------------------------------------------------
__global__ void __launch_bounds__(128) ln1_kernel(
    const float* __restrict__ x, const float* __restrict__ g,
    const float* __restrict__ bb)
{
    int t   = blockIdx.x;
    int win = t / Nn49, n = t % Nn49;
    int b   = win >> 6, wi = win & 63;
    int wy  = wi >> 3,  wx = wi & 7;
    int py  = n / WIN,  px = n % WIN;
    int hh  = (wy*WIN + py + SHIFT) % Hh;
    int ww  = (wx*WIN + px + SHIFT) % Wwid;
    const float* row = x + (((size_t)b*Hh + hh)*Wwid + ww) * Cc;

    int tid = threadIdx.x;
    float4 v = make_float4(0.f, 0.f, 0.f, 0.f);
    if (tid < 96) v = ((const float4*)row)[tid];
    float s  = v.x + v.y + v.z + v.w;
    float s2 = v.x*v.x + v.y*v.y + v.z*v.z + v.w*v.w;
#pragma unroll
    for (int off = 16; off; off >>= 1) {
        s  += __shfl_xor_sync(0xffffffffu, s,  off);
        s2 += __shfl_xor_sync(0xffffffffu, s2, off);
    }
    __shared__ float rs[4], rs2[4];
    if ((tid & 31) == 0) { rs[tid>>5] = s; rs2[tid>>5] = s2; }
    __syncthreads();
    s  = rs[0]  + rs[1]  + rs[2]  + rs[3];
    s2 = rs2[0] + rs2[1] + rs2[2] + rs2[3];
    float mu  = s * (1.f/384.f);
    float var = s2 * (1.f/384.f) - mu*mu;
    float inv = rsqrtf(var + 1e-5f);
    if (tid < 96) {
        float4 gv = ((const float4*)g)[tid];
        float4 bv = ((const float4*)bb)[tid];
        __half2 h0 = __floats2half2_rn((v.x - mu)*inv*gv.x + bv.x,
                                       (v.y - mu)*inv*gv.y + bv.y);
        __half2 h1 = __floats2half2_rn((v.z - mu)*inv*gv.z + bv.z,
                                       (v.w - mu)*inv*gv.w + bv.w);
        __half2* dst = (__half2*)(g_a + (size_t)t * Cc + tid*4);
        dst[0] = h0; dst[1] = h1;
    }
}

// ---------------------------------------------------------------------------
// MMA helpers
// ---------------------------------------------------------------------------
#define LDSM4(r0,r1,r2,r3,addr) \
    asm volatile("ldmatrix.sync.aligned.m8n8.x4.shared.b16 {%0,%1,%2,%3}, [%4];" \
        : "=r"(r0),"=r"(r1),"=r"(r2),"=r"(r3) : "r"(addr))

#define MMA16816(c, a, b) \
    asm volatile("mma.sync.aligned.m16n8k16.row.col.f32.f16.f16.f32 " \
        "{%0,%1,%2,%3},{%4,%5,%6,%7},{%8,%9},{%0,%1,%2,%3};" \
        : "+f"(c[0]),"+f"(c[1]),"+f"(c[2]),"+f"(c[3]) \
        : "r"(a[0]),"r"(a[1]),"r"(a[2]),"r"(a[3]),"r"(b[0]),"r"(b[1]))

__device__ __forceinline__ uint32_t smem_u32(const void* p) {
    return (uint32_t)__cvta_generic_to_shared(p);
}
__device__ __forceinline__ void cp_async16(uint32_t dst, const void* src) {
    asm volatile("cp.async.cg.shared.global [%0], [%1], 16;" :: "r"(dst), "l"(src));
}

// ---------------------------------------------------------------------------
// fp16 tensor-core GEMM (same as R3, proven)
// ---------------------------------------------------------------------------
template<int EPI>
__global__ void __launch_bounds__(256) hgemm(
    const __half* __restrict__ A, const __half* __restrict__ Wt,
    const float* __restrict__ bias, const float* __restrict__ resid,
    void* __restrict__ Cptr, int M, int Nd, int K)
{
    __shared__ __half As[2][128*40];
    __shared__ __half Bs[2][128*40];

    const int tid  = threadIdx.x;
    const int bm   = blockIdx.y * 128;
    const int bn   = blockIdx.x * 128;
    const int wid  = tid >> 5, lane = tid & 31;
    const int wm   = (wid & 1) * 64;
    const int wn   = (wid >> 1) * 32;

    float acc[4][4][4];
#pragma unroll
    for (int mi = 0; mi < 4; mi++)
#pragma unroll
        for (int ni = 0; ni < 4; ni++)
#pragma unroll
            for (int q = 0; q < 4; q++) acc[mi][ni][q] = 0.f;

    const int lr = tid >> 2;
    const int lc = (tid & 3) * 8;

    {
#pragma unroll
        for (int i = 0; i < 2; i++) {
            int row = lr + i*64;
            cp_async16(smem_u32(&As[0][row*40 + lc]), A  + (size_t)(bm+row)*K + lc);
            cp_async16(smem_u32(&Bs[0][row*40 + lc]), Wt + (size_t)(bn+row)*K + lc);
        }
        asm volatile("cp.async.commit_group;");
    }

    const int nk = K >> 5;
    for (int kt = 0; kt < nk; kt++) {
        const int s = kt & 1;
        if (kt + 1 < nk) {
            int k0 = (kt+1) << 5;
#pragma unroll
            for (int i = 0; i < 2; i++) {
                int row = lr + i*64;
                cp_async16(smem_u32(&As[s^1][row*40 + lc]), A  + (size_t)(bm+row)*K + k0 + lc);
                cp_async16(smem_u32(&Bs[s^1][row*40 + lc]), Wt + (size_t)(bn+row)*K + k0 + lc);
            }
            asm volatile("cp.async.commit_group;");
            asm volatile("cp.async.wait_group 1;");
        } else {
            asm volatile("cp.async.wait_group 0;");
        }
        __syncthreads();

#pragma unroll
        for (int kk = 0; kk < 2; kk++) {
            uint32_t a[4][4], b[4][2];
#pragma unroll
            for (int mi = 0; mi < 4; mi++) {
                int row = wm + mi*16 + (lane & 15);
                int col = kk*16 + ((lane >> 4) << 3);
                uint32_t ad = smem_u32(&As[s][row*40 + col]);
                LDSM4(a[mi][0], a[mi][1], a[mi][2], a[mi][3], ad);
            }
#pragma unroll
            for (int bi = 0; bi < 2; bi++) {
                int n   = wn + bi*16 + ((lane >> 4) << 3) + (lane & 7);
                int col = kk*16 + ((lane >> 3) & 1) * 8;
                uint32_t ad = smem_u32(&Bs[s][n*40 + col]);
                uint32_t t0, t1, t2, t3;
                LDSM4(t0, t1, t2, t3, ad);
                b[bi*2+0][0] = t0; b[bi*2+0][1] = t1;
                b[bi*2+1][0] = t2; b[bi*2+1][1] = t3;
            }
#pragma unroll
            for (int mi = 0; mi < 4; mi++)
#pragma unroll
                for (int ni = 0; ni < 4; ni++)
                    MMA16816(acc[mi][ni], a[mi], b[ni]);
        }
        __syncthreads();
    }

    const int er = lane >> 2, ec = (lane & 3) * 2;
#pragma unroll
    for (int mi = 0; mi < 4; mi++) {
#pragma unroll
        for (int ni = 0; ni < 4; ni++) {
            int col = bn + wn + ni*8 + ec;
            float b0 = bias[col], b1 = bias[col+1];
#pragma unroll
            for (int hh = 0; hh < 2; hh++) {
                size_t row = (size_t)(bm + wm + mi*16 + er + hh*8);
                float v0 = acc[mi][ni][hh*2+0] + b0;
                float v1 = acc[mi][ni][hh*2+1] + b1;
                if (EPI == 1) {
                    v0 = 0.5f * v0 * (1.0f + erff(v0 * 0.70710678118654752f));
                    v1 = 0.5f * v1 * (1.0f + erff(v1 * 0.70710678118654752f));
                }
                if (EPI == 3) {
                    const float* rr = resid + row * Nd + col;
                    v0 += rr[0]; v1 += rr[1];
                }
                if (EPI == 0 || EPI == 1) {
                    *(__half2*)((__half*)Cptr + row * Nd + col) = __floats2half2_rn(v0, v1);
                } else {
                    float2 f; f.x = v0; f.y = v1;
                    *(float2*)((float*)Cptr + row * Nd + col) = f;
                }
            }
        }
    }
}

// ---------------------------------------------------------------------------
// Tensor-core window attention: block = (window, head), 4 warps.
// S=QK^T via mma (49->64 pad), in-register softmax, P@V via mma.
// ---------------------------------------------------------------------------
__global__ void __launch_bounds__(128) attn_kernel(const float* __restrict__ lscale)
{
    const int win = blockIdx.x;
    const int h   = blockIdx.y;
    const int wm  = win & 63;
    const int tid = threadIdx.x;
    const int warp = tid >> 5, lane = tid & 31;

    __shared__ __half qs[64*40];   // q (normalized, scaled)
    __shared__ __half ks[64*40];   // k (normalized)
    __shared__ __half vt[32*72];   // v transposed [d][j]
    __shared__ __half ps[64*72];   // softmax probs

    // zero all smem (padding correctness for mma)
    {
        uint4 z = make_uint4(0,0,0,0);
        uint4* q4 = (uint4*)qs; uint4* k4 = (uint4*)ks;
        for (int i = tid; i < 320; i += 128) { q4[i] = z; k4[i] = z; }
        uint4* v4 = (uint4*)vt;
        for (int i = tid; i < 288; i += 128) v4[i] = z;
        uint4* p4 = (uint4*)ps;
        for (int i = tid; i < 576; i += 128) p4[i] = z;
    }
    __syncthreads();

    // load q,k,v; v stored transposed
    const __half* base = g_qkv + (size_t)(win*Nn49) * (3*Cc) + h*HD;
    for (int idx = tid; idx < Nn49*4; idx += 128) {
        int row = idx >> 2;
        int c   = (idx & 3) * 8;
        const __half* rb = base + (size_t)row * (3*Cc) + c;
        uint4 qv = *(const uint4*)(rb);
        uint4 kv = *(const uint4*)(rb + Cc);
        uint4 vv = *(const uint4*)(rb + 2*Cc);
        *(uint4*)(qs + row*40 + c) = qv;
        *(uint4*)(ks + row*40 + c) = kv;
        __half hb[8]; *(uint4*)hb = vv;
#pragma unroll
        for (int m = 0; m < 8; m++) vt[(c+m)*72 + row] = hb[m];
    }
    __syncthreads();

    // normalize q (fold logit scale) and k rows
    {
        float scale_h = __expf(fminf(lscale[h], 4.6051701859880914f));
        int r = -1; bool isq = false;
        if (tid < Nn49) { r = tid; isq = true; }
        else if (tid >= 64 && tid < 64 + Nn49) { r = tid - 64; }
        if (r >= 0) {
            __half* row = (isq ? qs : ks) + r*40;
            float ss = 0.f;
#pragma unroll
            for (int d = 0; d < HD; d += 2) {
                float2 f = __half22float2(*(__half2*)(row + d));
                ss += f.x*f.x + f.y*f.y;
            }
            float inv = 1.0f / fmaxf(sqrtf(ss), 1e-12f);
            if (isq) inv *= scale_h;
#pragma unroll
            for (int d = 0; d < HD; d += 2) {
                __half2* p = (__half2*)(row + d);
                float2 f = __half22float2(*p);
                *p = __floats2half2_rn(f.x*inv, f.y*inv);
            }
        }
    }
    __syncthreads();

    // S = Q @ K^T  (M=64 rows, N=56 (7 tiles), K=32)
    float s[7][4];
#pragma unroll
    for (int t = 0; t < 7; t++)
#pragma unroll
        for (int c = 0; c < 4; c++) s[t][c] = 0.f;

#pragma unroll
    for (int kk = 0; kk < 2; kk++) {
        uint32_t a[4];
        {
            int row = warp*16 + (lane & 15);
            int col = kk*16 + ((lane >> 4) << 3);
            LDSM4(a[0], a[1], a[2], a[3], smem_u32(qs + row*40 + col));
        }
        uint32_t b[8][2];
#pragma unroll
        for (int bi = 0; bi < 4; bi++) {
            int n   = bi*16 + ((lane >> 4) << 3) + (lane & 7);
            int col = kk*16 + ((lane >> 3) & 1) * 8;
            uint32_t t0, t1, t2, t3;
            LDSM4(t0, t1, t2, t3, smem_u32(ks + n*40 + col));
            b[bi*2+0][0] = t0; b[bi*2+0][1] = t1;
            b[bi*2+1][0] = t2; b[bi*2+1][1] = t3;
        }
#pragma unroll
        for (int t = 0; t < 7; t++)
            MMA16816(s[t], a, b[t]);
    }

    // epilogue: bias + masked softmax (rows i0, i1 per lane)
    {
        const float* bias = g_bias + ((size_t)wm*HEADS + h) * (Nn49*Nn49);
        int r0 = lane >> 2;
        int i0 = warp*16 + r0;
        int i1 = i0 + 8;
        int jb = (lane & 3) * 2;
#pragma unroll
        for (int t = 0; t < 7; t++) {
#pragma unroll
            for (int c = 0; c < 4; c++) {
                int i = (c >= 2) ? i1 : i0;
                int j = t*8 + jb + (c & 1);
                s[t][c] = (i < Nn49 && j < Nn49) ? s[t][c] + bias[i*Nn49 + j]
                                                 : -1e30f;
            }
        }
        float mx0 = -1e30f, mx1 = -1e30f;
#pragma unroll
        for (int t = 0; t < 7; t++) {
            mx0 = fmaxf(mx0, fmaxf(s[t][0], s[t][1]));
            mx1 = fmaxf(mx1, fmaxf(s[t][2], s[t][3]));
        }
#pragma unroll
        for (int off = 1; off <= 2; off <<= 1) {
            mx0 = fmaxf(mx0, __shfl_xor_sync(0xffffffffu, mx0, off));
            mx1 = fmaxf(mx1, __shfl_xor_sync(0xffffffffu, mx1, off));
        }
        float sm0 = 0.f, sm1 = 0.f;
#pragma unroll
        for (int t = 0; t < 7; t++) {
            s[t][0] = __expf(s[t][0] - mx0); sm0 += s[t][0];
            s[t][1] = __expf(s[t][1] - mx0); sm0 += s[t][1];
            s[t][2] = __expf(s[t][2] - mx1); sm1 += s[t][2];
            s[t][3] = __expf(s[t][3] - mx1); sm1 += s[t][3];
        }
#pragma unroll
        for (int off = 1; off <= 2; off <<= 1) {
            sm0 += __shfl_xor_sync(0xffffffffu, sm0, off);
            sm1 += __shfl_xor_sync(0xffffffffu, sm1, off);
        }
        float inv0 = 1.0f / sm0, inv1 = 1.0f / sm1;
#pragma unroll
        for (int t = 0; t < 7; t++) {
            int j0 = t*8 + jb;
            *(__half2*)(ps + (i0 & 63)*72 + j0) = __floats2half2_rn(s[t][0]*inv0, s[t][1]*inv0);
            *(__half2*)(ps + (i1 & 63)*72 + j0) = __floats2half2_rn(s[t][2]*inv1, s[t][3]*inv1);
        }
    }
    __syncwarp();

    // O = P @ V  (M=64, N=32 (4 tiles), K=64)
    float o[4][4];
#pragma unroll
    for (int t = 0; t < 4; t++)
#pragma unroll
        for (int c = 0; c < 4; c++) o[t][c] = 0.f;

#pragma unroll
    for (int kk = 0; kk < 4; kk++) {
        uint32_t a[4];
        {
            int row = warp*16 + (lane & 15);
            int col = kk*16 + ((lane >> 4) << 3);
            LDSM4(a[0], a[1], a[2], a[3], smem_u32(ps + row*72 + col));
        }
        uint32_t b[4][2];
#pragma unroll
        for (int bi = 0; bi < 2; bi++) {
            int n   = bi*16 + ((lane >> 4) << 3) + (lane & 7);
            int col = kk*16 + ((lane >> 3) & 1) * 8;
            uint32_t t0, t1, t2, t3;
            LDSM4(t0, t1, t2, t3, smem_u32(vt + n*72 + col));
            b[bi*2+0][0] = t0; b[bi*2+0][1] = t1;
            b[bi*2+1][0] = t2; b[bi*2+1][1] = t3;
        }
#pragma unroll
        for (int t = 0; t < 4; t++)
            MMA16816(o[t], a, b[t]);
    }

    // store O
    {
        int r0 = lane >> 2;
        int i0 = warp*16 + r0;
        int i1 = i0 + 8;
        int d0 = (lane & 3) * 2;
#pragma unroll
        for (int t = 0; t < 4; t++) {
            int d = t*8 + d0;
            if (i0 < Nn49)
                *(__half2*)(g_o + (size_t)(win*Nn49 + i0)*Cc + h*HD + d) =
                    __floats2half2_rn(o[t][0], o[t][1]);
            if (i1 < Nn49)
                *(__half2*)(g_o + (size_t)(win*Nn49 + i1)*Cc + h*HD + d) =
                    __floats2half2_rn(o[t][2], o[t][3]);
        }
    }
}

// ---------------------------------------------------------------------------
// window-reverse + un-shift + residual + LN2 -> g_x2 (fp32), g_xm (fp16)
// ---------------------------------------------------------------------------
__global__ void __launch_bounds__(128) ln2_kernel(
    const float* __restrict__ x, const float* __restrict__ g,
    const float* __restrict__ bb)
{
    int s_tok = blockIdx.x;
    int b   = s_tok / (Hh*Wwid);
    int rem = s_tok % (Hh*Wwid);
    int hh  = rem / Wwid, ww = rem % Wwid;
    int sh  = (hh + Hh - SHIFT) % Hh;
    int sw  = (ww + Wwid - SHIFT) % Wwid;
    int wy  = sh / WIN, py = sh % WIN;
    int wx  = sw / WIN, px = sw % WIN;
    size_t ptok = ((size_t)(b*NW + wy*8 + wx) * Nn49 + py*WIN + px);

    const float* xrow = x         + (size_t)s_tok * Cc;
    const float* prow = g_projout + ptok * Cc;

    int tid = threadIdx.x;
    float4 v = make_float4(0.f, 0.f, 0.f, 0.f);
    if (tid < 96) {
        float4 xv = ((const float4*)xrow)[tid];
        float4 pv = ((const float4*)prow)[tid];
        v = make_float4(xv.x + pv.x, xv.y + pv.y, xv.z + pv.z, xv.w + pv.w);
    }
    float s  = v.x + v.y + v.z + v.w;
    float s2 = v.x*v.x + v.y*v.y + v.z*v.z + v.w*v.w;
#pragma unroll
    for (int off = 16; off; off >>= 1) {
        s  += __shfl_xor_sync(0xffffffffu, s,  off);
        s2 += __shfl_xor_sync(0xffffffffu, s2, off);
    }
    __shared__ float rs[4], rs2[4];
    if ((tid & 31) == 0) { rs[tid>>5] = s; rs2[tid>>5] = s2; }
    __syncthreads();
    s  = rs[0]  + rs[1]  + rs[2]  + rs[3];
    s2 = rs2[0] + rs2[1] + rs2[2] + rs2[3];
    float mu  = s * (1.f/384.f);
    float var = s2 * (1.f/384.f) - mu*mu;
    float inv = rsqrtf(var + 1e-5f);
    if (tid < 96) {
        ((float4*)(g_x2 + (size_t)s_tok * Cc))[tid] = v;
        float4 gv = ((const float4*)g)[tid];
        float4 bv = ((const float4*)bb)[tid];
        __half2 h0 = __floats2half2_rn((v.x - mu)*inv*gv.x + bv.x,
                                       (v.y - mu)*inv*gv.y + bv.y);
        __half2 h1 = __floats2half2_rn((v.z - mu)*inv*gv.z + bv.z,
                                       (v.w - mu)*inv*gv.w + bv.w);
        __half2* dst = (__half2*)(g_xm + (size_t)s_tok * Cc + tid*4);
        dst[0] = h0; dst[1] = h1;
    }
}

// ---------------------------------------------------------------------------
extern "C" void kernel_launch(void* const* d_in, const int* in_sizes, int n_in,
                              void* d_out, int out_size)
{
    const float* x       = (const float*)d_in[0];
    const float* mask    = (const float*)d_in[1];
    const float* n1g     = (const float*)d_in[2];
    const float* n1b     = (const float*)d_in[3];
    const float* qkv_w   = (const float*)d_in[4];
    const float* qkv_b   = (const float*)d_in[5];
    const float* proj_w  = (const float*)d_in[6];
    const float* proj_b  = (const float*)d_in[7];
    const float* cpb_w1  = (const float*)d_in[8];
    const float* cpb_b1  = (const float*)d_in[9];
    const float* cpb_w2  = (const float*)d_in[10];
    const float* lscale  = (const float*)d_in[11];
    const float* n2g     = (const float*)d_in[12];
    const float* n2b     = (const float*)d_in[13];
    const float* mlp_w1  = (const float*)d_in[14];
    const float* mlp_b1  = (const float*)d_in[15];
    const float* mlp_w2  = (const float*)d_in[16];
    const float* mlp_b2  = (const float*)d_in[17];
    float* out = (float*)d_out;

    __half *a=nullptr, *qkv=nullptr, *o=nullptr, *xm=nullptr, *hidden=nullptr;
    __half *wqkv=nullptr, *wproj=nullptr, *wm1=nullptr, *wm2=nullptr;
    float *projout=nullptr, *x2=nullptr;
    cudaGetSymbolAddress((void**)&a,       g_a);
    cudaGetSymbolAddress((void**)&qkv,     g_qkv);
    cudaGetSymbolAddress((void**)&o,       g_o);
    cudaGetSymbolAddress((void**)&projout, g_projout);
    cudaGetSymbolAddress((void**)&x2,      g_x2);
    cudaGetSymbolAddress((void**)&xm,      g_xm);
    cudaGetSymbolAddress((void**)&hidden,  g_hidden);
    cudaGetSymbolAddress((void**)&wqkv,    g_wqkv);
    cudaGetSymbolAddress((void**)&wproj,   g_wproj);
    cudaGetSymbolAddress((void**)&wm1,     g_wm1);
    cudaGetSymbolAddress((void**)&wm2,     g_wm2);

    // weight conversion fp32 -> fp16
    f2h_kernel<<<(3*Cc*Cc + 255)/256, 256>>>(qkv_w,  wqkv,  3*Cc*Cc);
    f2h_kernel<<<(Cc*Cc + 255)/256,   256>>>(proj_w, wproj, Cc*Cc);
    f2h_kernel<<<(HIDDEN*Cc + 255)/256, 256>>>(mlp_w1, wm1, HIDDEN*Cc);
    f2h_kernel<<<(Cc*HIDDEN + 255)/256, 256>>>(mlp_w2, wm2, Cc*HIDDEN);

    // CPB table, then fused rpb+mask bias table
    cpb_kernel<<<169, 256>>>(cpb_w1, cpb_b1, cpb_w2);
    bias_kernel<<<dim3(NW, HEADS), 256>>>(mask);
    // LN1 + shift + window partition
    ln1_kernel<<<TOK, 128>>>(x, n1g, n1b);
    // QKV GEMM -> fp16
    hgemm<0><<<dim3(9, TOK/128), 256>>>(a, wqkv, qkv_b, nullptr, qkv, TOK, 3*Cc, Cc);
    // tensor-core window attention
    attn_kernel<<<dim3(NWIN, HEADS), 128>>>(lscale);
    // proj GEMM -> fp32
    hgemm<2><<<dim3(3, TOK/128), 256>>>(o, wproj, proj_b, nullptr, projout, TOK, Cc, Cc);
    // window-reverse + residual + LN2
    ln2_kernel<<<TOK, 128>>>(x, n2g, n2b);
    // MLP1 + GELU -> fp16
    hgemm<1><<<dim3(6, TOK/128), 256>>>(xm, wm1, mlp_b1, nullptr, hidden, TOK, HIDDEN, Cc);
    // MLP2 + residual -> d_out (fp32)
    hgemm<3><<<dim3(3, TOK/128), 256>>>(hidden, wm2, mlp_b2, x2, out, TOK, Cc, HIDDEN);
}